// round 2
// baseline (speedup 1.0000x reference)
#include <cuda_runtime.h>

// Problem shape (fixed by setup_inputs)
#define NN   100000
#define DIM1 128      // F_in = heads1*hid = 128
#define H1   4
#define F2   40

// ---------------- scratch (device globals: allocation-free) ----------------
__device__ float g_xw1[(long)NN * DIM1];    // layer1 x@W1          [N,128]
__device__ float g_h  [(long)NN * DIM1];    // layer1 output (relu) [N,128]
__device__ float g_asrc1[NN * H1];
__device__ float g_adst1[NN * H1];
__device__ float g_den1 [NN * H1];
__device__ float g_xw2[(long)NN * F2];      // layer2 h@W2          [N,40]
__device__ float g_asrc2[NN];
__device__ float g_adst2[NN];
__device__ float g_den2 [NN];

__device__ __forceinline__ float leaky(float v) { return v > 0.f ? v : 0.2f * v; }

__device__ __forceinline__ void red_add_v4(float* addr, float4 v) {
    asm volatile("red.global.add.v4.f32 [%0], {%1, %2, %3, %4};"
                 :: "l"(addr), "f"(v.x), "f"(v.y), "f"(v.z), "f"(v.w)
                 : "memory");
}

// ---------------- GEMM1: g_xw1 = x @ W1  ([N,128] @ [128,128]) --------------
// block = 256 threads, 32 rows/block. K split into 2 tiles of 64.
__global__ void gemm1_kernel(const float* __restrict__ x, const float* __restrict__ W,
                             int N) {
    __shared__ float sW[64][128];   // 32KB
    __shared__ float sx[32][64];    // 8KB
    int rowBase = blockIdx.x * 32;
    int tid  = threadIdx.x;
    int warp = tid >> 5, lane = tid & 31;

    float4 acc[4];
#pragma unroll
    for (int r = 0; r < 4; ++r) acc[r] = make_float4(0.f, 0.f, 0.f, 0.f);

    for (int kt = 0; kt < 2; ++kt) {
        __syncthreads();
        for (int i = tid; i < 2048; i += 256) {
            int k = i >> 5, c4 = i & 31;
            ((float4*)&sW[k][0])[c4] =
                ((const float4*)(W + (long)(kt * 64 + k) * 128))[c4];
        }
        for (int i = tid; i < 512; i += 256) {
            int r = i >> 4, c4 = i & 15;
            int row = rowBase + r;
            if (row < N)
                ((float4*)&sx[r][0])[c4] =
                    ((const float4*)(x + (long)row * 128 + kt * 64))[c4];
        }
        __syncthreads();
#pragma unroll 4
        for (int k = 0; k < 64; ++k) {
            float4 w = ((float4*)&sW[k][0])[lane];
#pragma unroll
            for (int r = 0; r < 4; ++r) {
                float xv = sx[warp * 4 + r][k];
                acc[r].x += xv * w.x; acc[r].y += xv * w.y;
                acc[r].z += xv * w.z; acc[r].w += xv * w.w;
            }
        }
    }
#pragma unroll
    for (int r = 0; r < 4; ++r) {
        int row = rowBase + warp * 4 + r;
        if (row < N)
            ((float4*)(g_xw1 + (long)row * 128))[lane] = acc[r];
    }
}

// ---------------- att dots layer1: a_src[n,h], a_dst[n,h] -------------------
__global__ void att1_kernel(const float* __restrict__ att_s,
                            const float* __restrict__ att_d, int N) {
    int n = blockIdx.x * 8 + (threadIdx.x >> 5);
    int lane = threadIdx.x & 31;
    if (n >= N) return;
    float4 v = ((const float4*)(g_xw1 + (long)n * DIM1))[lane];
    float4 a = ((const float4*)att_s)[lane];
    float4 b = ((const float4*)att_d)[lane];
    float ps = v.x * a.x + v.y * a.y + v.z * a.z + v.w * a.w;
    float pd = v.x * b.x + v.y * b.y + v.z * b.z + v.w * b.w;
#pragma unroll
    for (int o = 4; o; o >>= 1) {
        ps += __shfl_xor_sync(0xffffffffu, ps, o);
        pd += __shfl_xor_sync(0xffffffffu, pd, o);
    }
    if ((lane & 7) == 0) {
        int head = lane >> 3;
        g_asrc1[n * H1 + head] = ps;
        g_adst1[n * H1 + head] = pd;
    }
}

// ---------------- zero scratch for layer1 ----------------------------------
__global__ void zero1_kernel(int N) {
    long total = (long)N * DIM1 + (long)N * H1;
    for (long i = (long)blockIdx.x * blockDim.x + threadIdx.x; i < total;
         i += (long)gridDim.x * blockDim.x) {
        if (i < (long)N * DIM1) g_h[i] = 0.f;
        else g_den1[i - (long)N * DIM1] = 0.f;
    }
}

// ---------------- layer1 softmax denominator (thread per edge) -------------
__global__ void den1_kernel(const int* __restrict__ ei, int E, int N) {
    int e = blockIdx.x * blockDim.x + threadIdx.x;
    int EP = E + N;
    if (e >= EP) return;
    int src, dst;
    if (e < E) { src = ei[e]; dst = ei[E + e]; }
    else       { src = e - E; dst = src; }
    float4 as = ((const float4*)g_asrc1)[src];
    float4 ad = ((const float4*)g_adst1)[dst];
    float s0 = __expf(leaky(as.x + ad.x));
    float s1 = __expf(leaky(as.y + ad.y));
    float s2 = __expf(leaky(as.z + ad.z));
    float s3 = __expf(leaky(as.w + ad.w));
    atomicAdd(&g_den1[dst * 4 + 0], s0);
    atomicAdd(&g_den1[dst * 4 + 1], s1);
    atomicAdd(&g_den1[dst * 4 + 2], s2);
    atomicAdd(&g_den1[dst * 4 + 3], s3);
}

// ---------------- layer1 aggregate (warp per edge) --------------------------
__global__ void agg1_kernel(const int* __restrict__ ei, int E, int N) {
    int warp = threadIdx.x >> 5, lane = threadIdx.x & 31;
    long e = (long)blockIdx.x * 8 + warp;
    int EP = E + N;
    if (e >= EP) return;
    int src = 0, dst = 0;
    if (lane == 0) {
        if (e < E) { src = ei[e]; dst = ei[E + e]; }
        else       { src = (int)(e - E); dst = src; }
    }
    src = __shfl_sync(0xffffffffu, src, 0);
    dst = __shfl_sync(0xffffffffu, dst, 0);
    int head = lane >> 3;
    float s = g_asrc1[src * 4 + head] + g_adst1[dst * 4 + head];
    float alpha = __expf(leaky(s)) / g_den1[dst * 4 + head];
    float4 v = ((const float4*)(g_xw1 + (long)src * DIM1))[lane];
    v.x *= alpha; v.y *= alpha; v.z *= alpha; v.w *= alpha;
    red_add_v4(g_h + (long)dst * DIM1 + lane * 4, v);
}

// ---------------- layer1 epilogue: h = relu(h + b1) -------------------------
__global__ void epi1_kernel(const float* __restrict__ b1, int N) {
    long total = (long)N * DIM1;
    for (long i = (long)blockIdx.x * blockDim.x + threadIdx.x; i < total;
         i += (long)gridDim.x * blockDim.x) {
        float v = g_h[i] + b1[i & (DIM1 - 1)];
        g_h[i] = v > 0.f ? v : 0.f;
    }
}

// ---------------- GEMM2: g_xw2 = h @ W2  ([N,128] @ [128,40]) ---------------
__global__ void gemm2_kernel(const float* __restrict__ W2, int N) {
    __shared__ float sx[32][128];   // 16KB
    __shared__ float sW[128 * 40];  // 20KB
    int rowBase = blockIdx.x * 32;
    int tid = threadIdx.x, warp = tid >> 5, lane = tid & 31;
    for (int i = tid; i < 1280; i += 256)
        ((float4*)sW)[i] = ((const float4*)W2)[i];
    for (int i = tid; i < 1024; i += 256) {
        int r = i >> 5;
        if (rowBase + r < N)
            ((float4*)sx)[i] = ((const float4*)(g_h + (long)rowBase * 128))[i];
    }
    __syncthreads();

    float acc0[4] = {0.f, 0.f, 0.f, 0.f};
    float acc1[4] = {0.f, 0.f, 0.f, 0.f};
    bool hi = lane < 8;
#pragma unroll 4
    for (int k = 0; k < 128; ++k) {
        float w0 = sW[k * 40 + lane];
        float w1 = hi ? sW[k * 40 + 32 + lane] : 0.f;
#pragma unroll
        for (int r = 0; r < 4; ++r) {
            float xv = sx[warp * 4 + r][k];
            acc0[r] += xv * w0;
            acc1[r] += xv * w1;
        }
    }
#pragma unroll
    for (int r = 0; r < 4; ++r) {
        long row = rowBase + warp * 4 + r;
        if (row < N) {
            g_xw2[row * F2 + lane] = acc0[r];
            if (hi) g_xw2[row * F2 + 32 + lane] = acc1[r];
        }
    }
}

// ---------------- att dots layer2 -------------------------------------------
__global__ void att2_kernel(const float* __restrict__ att_s,
                            const float* __restrict__ att_d, int N) {
    int n = blockIdx.x * 8 + (threadIdx.x >> 5);
    int lane = threadIdx.x & 31;
    if (n >= N) return;
    float ps = 0.f, pd = 0.f;
    if (lane < 10) {
        float4 v = ((const float4*)(g_xw2 + (long)n * F2))[lane];
        float4 a = ((const float4*)att_s)[lane];
        float4 b = ((const float4*)att_d)[lane];
        ps = v.x * a.x + v.y * a.y + v.z * a.z + v.w * a.w;
        pd = v.x * b.x + v.y * b.y + v.z * b.z + v.w * b.w;
    }
#pragma unroll
    for (int o = 16; o; o >>= 1) {
        ps += __shfl_xor_sync(0xffffffffu, ps, o);
        pd += __shfl_xor_sync(0xffffffffu, pd, o);
    }
    if (lane == 0) { g_asrc2[n] = ps; g_adst2[n] = pd; }
}

// ---------------- zero scratch for layer2 (den2 + d_out) --------------------
__global__ void zero2_kernel(float* __restrict__ out, int N) {
    long total = (long)N * F2 + N;
    for (long i = (long)blockIdx.x * blockDim.x + threadIdx.x; i < total;
         i += (long)gridDim.x * blockDim.x) {
        if (i < (long)N * F2) out[i] = 0.f;
        else g_den2[i - (long)N * F2] = 0.f;
    }
}

// ---------------- layer2 softmax denominator --------------------------------
__global__ void den2_kernel(const int* __restrict__ ei, int E, int N) {
    int e = blockIdx.x * blockDim.x + threadIdx.x;
    int EP = E + N;
    if (e >= EP) return;
    int src, dst;
    if (e < E) { src = ei[e]; dst = ei[E + e]; }
    else       { src = e - E; dst = src; }
    float s = __expf(leaky(g_asrc2[src] + g_adst2[dst]));
    atomicAdd(&g_den2[dst], s);
}

// ---------------- layer2 aggregate (warp per edge, into d_out) --------------
__global__ void agg2_kernel(const int* __restrict__ ei,
                            float* __restrict__ out, int E, int N) {
    int warp = threadIdx.x >> 5, lane = threadIdx.x & 31;
    long e = (long)blockIdx.x * 8 + warp;
    int EP = E + N;
    if (e >= EP) return;
    int src = 0, dst = 0;
    if (lane == 0) {
        if (e < E) { src = ei[e]; dst = ei[E + e]; }
        else       { src = (int)(e - E); dst = src; }
    }
    src = __shfl_sync(0xffffffffu, src, 0);
    dst = __shfl_sync(0xffffffffu, dst, 0);
    float s = g_asrc2[src] + g_adst2[dst];
    float alpha = __expf(leaky(s)) / g_den2[dst];
    if (lane < 10) {
        float4 v = ((const float4*)(g_xw2 + (long)src * F2))[lane];
        v.x *= alpha; v.y *= alpha; v.z *= alpha; v.w *= alpha;
        red_add_v4(out + (long)dst * F2 + lane * 4, v);
    }
}

// ---------------- final bias add --------------------------------------------
__global__ void bias2_kernel(float* __restrict__ out, const float* __restrict__ b2,
                             int N) {
    long total = (long)N * F2;
    for (long i = (long)blockIdx.x * blockDim.x + threadIdx.x; i < total;
         i += (long)gridDim.x * blockDim.x) {
        int col = (int)(i - (i / F2) * F2);
        out[i] += b2[col];
    }
}

// ============================================================================
extern "C" void kernel_launch(void* const* d_in, const int* in_sizes, int n_in,
                              void* d_out, int out_size) {
    const float* x   = (const float*)d_in[0];
    const int*   ei  = (const int*)d_in[1];     // int64 downcast to int32 by JAX default config
    const float* W1  = (const float*)d_in[2];
    const float* as1 = (const float*)d_in[3];
    const float* ad1 = (const float*)d_in[4];
    const float* b1  = (const float*)d_in[5];
    const float* W2  = (const float*)d_in[6];
    const float* as2 = (const float*)d_in[7];
    const float* ad2 = (const float*)d_in[8];
    const float* b2  = (const float*)d_in[9];
    float*       out = (float*)d_out;

    int N  = in_sizes[0] / DIM1;   // 100000
    int E  = in_sizes[1] / 2;      // 1600000
    int EP = E + N;

    // ---- layer 1 ----
    gemm1_kernel<<<(N + 31) / 32, 256>>>(x, W1, N);
    att1_kernel<<<(N + 7) / 8, 256>>>(as1, ad1, N);
    zero1_kernel<<<4096, 256>>>(N);
    den1_kernel<<<(EP + 255) / 256, 256>>>(ei, E, N);
    agg1_kernel<<<(EP + 7) / 8, 256>>>(ei, E, N);
    epi1_kernel<<<4096, 256>>>(b1, N);

    // ---- layer 2 ----
    gemm2_kernel<<<(N + 31) / 32, 256>>>(W2, N);
    att2_kernel<<<(N + 7) / 8, 256>>>(as2, ad2, N);
    zero2_kernel<<<2048, 256>>>(out, N);
    den2_kernel<<<(EP + 255) / 256, 256>>>(ei, E, N);
    agg2_kernel<<<(EP + 7) / 8, 256>>>(ei, out, E, N);
    bias2_kernel<<<2048, 256>>>(out, b2, N);
}

// round 3
// speedup vs baseline: 1.1497x; 1.1497x over previous
#include <cuda_runtime.h>

#define NN   100000
#define DIM1 128
#define H1   4
#define F2   40

// ---------------- scratch (device globals: allocation-free) ----------------
__device__ float g_xw1[(size_t)NN * DIM1];   // layer1 x@W1           [N,128]
__device__ float g_h  [(size_t)NN * DIM1];   // layer1 numerator acc  [N,128]
__device__ float g_asrc1[NN * H1];
__device__ float g_adst1[NN * H1];
__device__ float g_den1 [NN * H1];
__device__ float g_xw2[(size_t)NN * F2];     // layer2 h@W2           [N,40]
__device__ float g_asrc2[NN];
__device__ float g_adst2[NN];
__device__ float g_den2 [NN];

__device__ __forceinline__ float leaky(float v) { return v > 0.f ? v : 0.2f * v; }

__device__ __forceinline__ void red_add_v4(float* addr, float4 v) {
    asm volatile("red.global.add.v4.f32 [%0], {%1, %2, %3, %4};"
                 :: "l"(addr), "f"(v.x), "f"(v.y), "f"(v.z), "f"(v.w) : "memory");
}
__device__ __forceinline__ void red_add_f32(float* addr, float v) {
    asm volatile("red.global.add.f32 [%0], %1;" :: "l"(addr), "f"(v) : "memory");
}
// Packed fp32x2 FMA (Blackwell FFMA2): d = a*b + d
__device__ __forceinline__ void fma2(unsigned long long& d,
                                     unsigned long long a, unsigned long long b) {
    asm("fma.rn.f32x2 %0, %1, %2, %0;" : "+l"(d) : "l"(a), "l"(b));
}
__device__ __forceinline__ unsigned long long pack2(float lo, float hi) {
    unsigned long long d;
    asm("mov.b64 %0, {%1, %2};" : "=l"(d) : "f"(lo), "f"(hi));
    return d;
}
__device__ __forceinline__ void unpack2(unsigned long long d, float& lo, float& hi) {
    asm("mov.b64 {%0, %1}, %2;" : "=f"(lo), "=f"(hi) : "l"(d));
}

// ---------------- zero all accumulators ------------------------------------
__global__ void zero_kernel(float* __restrict__ out, int N) {
    size_t nh = (size_t)N * DIM1, nd1 = (size_t)N * H1, no = (size_t)N * F2;
    size_t total = nh + nd1 + no + N;
    for (size_t i = (size_t)blockIdx.x * blockDim.x + threadIdx.x; i < total;
         i += (size_t)gridDim.x * blockDim.x) {
        if (i < nh) g_h[i] = 0.f;
        else if (i < nh + nd1) g_den1[i - nh] = 0.f;
        else if (i < nh + nd1 + no) out[i - nh - nd1] = 0.f;
        else g_den2[i - nh - nd1 - no] = 0.f;
    }
}

// ---------------- GEMM1 + fused attention dots ------------------------------
// 256 thr = 8 warps x 8 rows = 64 rows/block. FFMA2 inner loop.
__global__ __launch_bounds__(256) void gemm1_kernel(
    const float* __restrict__ x, const float* __restrict__ W,
    const float* __restrict__ att_s, const float* __restrict__ att_d, int N) {
    __shared__ float sW[64][128];   // 32KB
    __shared__ float sx[64][64];    // 16KB
    int rowBase = blockIdx.x * 64;
    int tid = threadIdx.x, warp = tid >> 5, lane = tid & 31;

    unsigned long long accLo[8], accHi[8];
#pragma unroll
    for (int r = 0; r < 8; ++r) { accLo[r] = 0ull; accHi[r] = 0ull; }

    for (int kt = 0; kt < 2; ++kt) {
        __syncthreads();
        for (int i = tid; i < 2048; i += 256) {          // W tile 64x128
            int k = i >> 5, c4 = i & 31;
            ((float4*)&sW[k][0])[c4] =
                ((const float4*)(W + (size_t)(kt * 64 + k) * 128))[c4];
        }
        for (int i = tid; i < 1024; i += 256) {          // x tile 64x64
            int r = i >> 4, c4 = i & 15;
            int row = rowBase + r;
            if (row < N)
                ((float4*)&sx[r][0])[c4] =
                    ((const float4*)(x + (size_t)row * 128 + kt * 64))[c4];
        }
        __syncthreads();
#pragma unroll 16
        for (int k = 0; k < 64; ++k) {
            float4 w = ((float4*)&sW[k][0])[lane];
            unsigned long long wlo = pack2(w.x, w.y), whi = pack2(w.z, w.w);
#pragma unroll
            for (int r = 0; r < 8; ++r) {
                float xv = sx[warp * 8 + r][k];
                unsigned long long xx = pack2(xv, xv);
                fma2(accLo[r], xx, wlo);
                fma2(accHi[r], xx, whi);
            }
        }
    }
    // epilogue: store row + per-head attention dots (head = lane>>3)
    float4 as4 = ((const float4*)att_s)[lane];
    float4 ad4 = ((const float4*)att_d)[lane];
#pragma unroll
    for (int r = 0; r < 8; ++r) {
        int row = rowBase + warp * 8 + r;
        float4 v;
        unpack2(accLo[r], v.x, v.y);
        unpack2(accHi[r], v.z, v.w);
        float ps = v.x * as4.x + v.y * as4.y + v.z * as4.z + v.w * as4.w;
        float pd = v.x * ad4.x + v.y * ad4.y + v.z * ad4.z + v.w * ad4.w;
#pragma unroll
        for (int o = 4; o; o >>= 1) {
            ps += __shfl_xor_sync(0xffffffffu, ps, o);
            pd += __shfl_xor_sync(0xffffffffu, pd, o);
        }
        if (row < N) {
            ((float4*)(g_xw1 + (size_t)row * 128))[lane] = v;
            if ((lane & 7) == 0) {
                g_asrc1[row * 4 + (lane >> 3)] = ps;
                g_adst1[row * 4 + (lane >> 3)] = pd;
            }
        }
    }
}

// ---------------- layer1 fused aggregate: numerator + denominator -----------
__global__ void agg1_kernel(const int* __restrict__ ei, int E, int N) {
    int warp = threadIdx.x >> 5, lane = threadIdx.x & 31;
    long e = (long)blockIdx.x * 8 + warp;
    if (e >= (long)E + N) return;
    int src, dst;
    if (e < E) { src = __ldg(ei + e); dst = __ldg(ei + E + e); }
    else       { src = (int)(e - E); dst = src; }
    int head = lane >> 3;
    float s = g_asrc1[src * 4 + head] + g_adst1[dst * 4 + head];
    float ex = __expf(leaky(s));
    float4 v = ((const float4*)(g_xw1 + (size_t)src * 128))[lane];
    v.x *= ex; v.y *= ex; v.z *= ex; v.w *= ex;
    red_add_v4(g_h + (size_t)dst * 128 + lane * 4, v);
    // one v4 red for all 4 head denominators
    float e0 = __shfl_sync(0xffffffffu, ex, 0);
    float e1 = __shfl_sync(0xffffffffu, ex, 8);
    float e2 = __shfl_sync(0xffffffffu, ex, 16);
    float e3 = __shfl_sync(0xffffffffu, ex, 24);
    if (lane == 0) red_add_v4(&g_den1[dst * 4], make_float4(e0, e1, e2, e3));
}

// ---------------- GEMM2 (fused: h=relu(num/den+b1) on load; att2 in epilogue)
// 256 thr = 8 warps x 4 rows = 32 rows/block. lanes 0..19 cover 40 cols (f32x2)
__global__ __launch_bounds__(256) void gemm2_kernel(
    const float* __restrict__ W2, const float* __restrict__ b1,
    const float* __restrict__ att_s, const float* __restrict__ att_d, int N) {
    __shared__ float sx[32][128];   // 16KB (post-activation h rows)
    __shared__ float sW[128 * 40];  // 20KB
    int rowBase = blockIdx.x * 32;
    int tid = threadIdx.x, warp = tid >> 5, lane = tid & 31;

    for (int i = tid; i < 1280; i += 256)
        ((float4*)sW)[i] = ((const float4*)W2)[i];
    for (int i = tid; i < 1024; i += 256) {
        int r = i >> 5, c4 = i & 31;
        int row = rowBase + r;
        if (row < N) {
            float4 v = ((const float4*)(g_h + (size_t)row * 128))[c4];
            float inv = 1.f / g_den1[row * 4 + (c4 >> 3)];
            float4 b = ((const float4*)b1)[c4];
            v.x = fmaxf(v.x * inv + b.x, 0.f);
            v.y = fmaxf(v.y * inv + b.y, 0.f);
            v.z = fmaxf(v.z * inv + b.z, 0.f);
            v.w = fmaxf(v.w * inv + b.w, 0.f);
            ((float4*)&sx[r][0])[c4] = v;
        } else {
            ((float4*)&sx[r][0])[c4] = make_float4(0.f, 0.f, 0.f, 0.f);
        }
    }
    __syncthreads();

    bool act = lane < 20;
    unsigned long long acc[4] = {0ull, 0ull, 0ull, 0ull};
#pragma unroll 8
    for (int k = 0; k < 128; ++k) {
        unsigned long long w = 0ull;
        if (act) {
            float2 w2 = *(const float2*)&sW[k * 40 + lane * 2];
            w = pack2(w2.x, w2.y);
        }
#pragma unroll
        for (int r = 0; r < 4; ++r) {
            float xv = sx[warp * 4 + r][k];
            unsigned long long xx = pack2(xv, xv);
            fma2(acc[r], xx, w);
        }
    }
    float2 as2 = act ? ((const float2*)att_s)[lane] : make_float2(0.f, 0.f);
    float2 ad2 = act ? ((const float2*)att_d)[lane] : make_float2(0.f, 0.f);
#pragma unroll
    for (int r = 0; r < 4; ++r) {
        int row = rowBase + warp * 4 + r;
        float c0, c1;
        unpack2(acc[r], c0, c1);
        float ps = c0 * as2.x + c1 * as2.y;
        float pd = c0 * ad2.x + c1 * ad2.y;
#pragma unroll
        for (int o = 16; o; o >>= 1) {
            ps += __shfl_xor_sync(0xffffffffu, ps, o);
            pd += __shfl_xor_sync(0xffffffffu, pd, o);
        }
        if (row < N) {
            if (act) *(float2*)(g_xw2 + (size_t)row * F2 + lane * 2) = make_float2(c0, c1);
            if (lane == 0) { g_asrc2[row] = ps; g_adst2[row] = pd; }
        }
    }
}

// ---------------- layer2 fused aggregate -------------------------------------
__global__ void agg2_kernel(const int* __restrict__ ei,
                            float* __restrict__ out, int E, int N) {
    int warp = threadIdx.x >> 5, lane = threadIdx.x & 31;
    long e = (long)blockIdx.x * 8 + warp;
    if (e >= (long)E + N) return;
    int src, dst;
    if (e < E) { src = __ldg(ei + e); dst = __ldg(ei + E + e); }
    else       { src = (int)(e - E); dst = src; }
    float s = g_asrc2[src] + g_adst2[dst];
    float ex = __expf(leaky(s));
    if (lane < 10) {
        float4 v = ((const float4*)(g_xw2 + (size_t)src * F2))[lane];
        v.x *= ex; v.y *= ex; v.z *= ex; v.w *= ex;
        red_add_v4(out + (size_t)dst * F2 + lane * 4, v);
    }
    if (lane == 31) red_add_f32(&g_den2[dst], ex);
}

// ---------------- final: out = out/den2 + b2 ---------------------------------
__global__ void final_kernel(float* __restrict__ out, const float* __restrict__ b2,
                             int N) {
    size_t total = (size_t)N * F2;
    for (size_t i = (size_t)blockIdx.x * blockDim.x + threadIdx.x; i < total;
         i += (size_t)gridDim.x * blockDim.x) {
        size_t n = i / F2;
        int c = (int)(i - n * F2);
        out[i] = out[i] / g_den2[n] + b2[c];
    }
}

// ============================================================================
extern "C" void kernel_launch(void* const* d_in, const int* in_sizes, int n_in,
                              void* d_out, int out_size) {
    const float* x   = (const float*)d_in[0];
    const int*   ei  = (const int*)d_in[1];   // int32 (JAX default-config downcast)
    const float* W1  = (const float*)d_in[2];
    const float* as1 = (const float*)d_in[3];
    const float* ad1 = (const float*)d_in[4];
    const float* b1  = (const float*)d_in[5];
    const float* W2  = (const float*)d_in[6];
    const float* as2 = (const float*)d_in[7];
    const float* ad2 = (const float*)d_in[8];
    const float* b2  = (const float*)d_in[9];
    float*       out = (float*)d_out;

    int N  = in_sizes[0] / DIM1;   // 100000
    int E  = in_sizes[1] / 2;      // 1600000
    int EP = E + N;

    zero_kernel <<<4096, 256>>>(out, N);
    gemm1_kernel<<<(N + 63) / 64, 256>>>(x, W1, as1, ad1, N);
    agg1_kernel <<<(EP + 7) / 8, 256>>>(ei, E, N);
    gemm2_kernel<<<(N + 31) / 32, 256>>>(W2, b1, as2, ad2, N);
    agg2_kernel <<<(EP + 7) / 8, 256>>>(ei, out, E, N);
    final_kernel<<<2048, 256>>>(out, b2, N);
}

// round 4
// speedup vs baseline: 1.4921x; 1.2978x over previous
#include <cuda_runtime.h>

#define NN   100000
#define DIM1 128
#define H1   4
#define F2   40

// ---------------- scratch (device globals: allocation-free) ----------------
__device__ float g_xw1[(size_t)NN * DIM1];   // layer1 x@W1           [N,128]
__device__ float g_h  [(size_t)NN * DIM1];   // layer1 numerator acc  [N,128]
__device__ float g_asrc1[NN * H1];
__device__ float g_adst1[NN * H1];
__device__ float g_den1 [NN * H1];
__device__ float g_xw2[(size_t)NN * F2];     // layer2 h@W2           [N,40]
__device__ float g_asrc2[NN];
__device__ float g_adst2[NN];
__device__ float g_den2 [NN];

__device__ __forceinline__ float leaky(float v) { return v > 0.f ? v : 0.2f * v; }

__device__ __forceinline__ void red_add_v4(float* addr, float4 v) {
    asm volatile("red.global.add.v4.f32 [%0], {%1, %2, %3, %4};"
                 :: "l"(addr), "f"(v.x), "f"(v.y), "f"(v.z), "f"(v.w) : "memory");
}
__device__ __forceinline__ void red_add_f32(float* addr, float v) {
    asm volatile("red.global.add.f32 [%0], %1;" :: "l"(addr), "f"(v) : "memory");
}
// Packed fp32x2 FMA (Blackwell FFMA2): d = a*b + d
__device__ __forceinline__ void fma2(unsigned long long& d,
                                     unsigned long long a, unsigned long long b) {
    asm("fma.rn.f32x2 %0, %1, %2, %0;" : "+l"(d) : "l"(a), "l"(b));
}
__device__ __forceinline__ unsigned long long pack2(float lo, float hi) {
    unsigned long long d;
    asm("mov.b64 %0, {%1, %2};" : "=l"(d) : "f"(lo), "f"(hi));
    return d;
}
__device__ __forceinline__ void unpack2(unsigned long long d, float& lo, float& hi) {
    asm("mov.b64 {%0, %1}, %2;" : "=f"(lo), "=f"(hi) : "l"(d));
}

// ---------------- zero all accumulators ------------------------------------
__global__ void zero_kernel(float* __restrict__ out, int N) {
    size_t nh = (size_t)N * DIM1, nd1 = (size_t)N * H1, no = (size_t)N * F2;
    size_t total = nh + nd1 + no + N;
    for (size_t i = (size_t)blockIdx.x * blockDim.x + threadIdx.x; i < total;
         i += (size_t)gridDim.x * blockDim.x) {
        if (i < nh) g_h[i] = 0.f;
        else if (i < nh + nd1) g_den1[i - nh] = 0.f;
        else if (i < nh + nd1 + no) out[i - nh - nd1] = 0.f;
        else g_den2[i - nh - nd1 - no] = 0.f;
    }
}

// ---------------- GEMM1 + fused attention dots ------------------------------
// 256 thr = 8 warps x 8 rows = 64 rows/block; k-vectorized float4 LDS.
__global__ __launch_bounds__(256) void gemm1_kernel(
    const float* __restrict__ x, const float* __restrict__ W,
    const float* __restrict__ att_s, const float* __restrict__ att_d, int N) {
    __shared__ float sW[64][128];   // 32KB
    __shared__ float sx[64][64];    // 16KB
    int rowBase = blockIdx.x * 64;
    int tid = threadIdx.x, warp = tid >> 5, lane = tid & 31;

    unsigned long long accLo[8], accHi[8];
#pragma unroll
    for (int r = 0; r < 8; ++r) { accLo[r] = 0ull; accHi[r] = 0ull; }

    for (int kt = 0; kt < 2; ++kt) {
        __syncthreads();
        for (int i = tid; i < 2048; i += 256) {          // W tile 64x128
            int k = i >> 5, c4 = i & 31;
            ((float4*)&sW[k][0])[c4] =
                ((const float4*)(W + (size_t)(kt * 64 + k) * 128))[c4];
        }
        for (int i = tid; i < 1024; i += 256) {          // x tile 64x64
            int r = i >> 4, c4 = i & 15;
            int row = rowBase + r;
            if (row < N)
                ((float4*)&sx[r][0])[c4] =
                    ((const float4*)(x + (size_t)row * 128 + kt * 64))[c4];
        }
        __syncthreads();
#pragma unroll
        for (int k4 = 0; k4 < 16; ++k4) {
            float4 xr[8];
#pragma unroll
            for (int r = 0; r < 8; ++r)
                xr[r] = ((float4*)&sx[warp * 8 + r][0])[k4];
#pragma unroll
            for (int kk = 0; kk < 4; ++kk) {
                float4 w = ((float4*)&sW[k4 * 4 + kk][0])[lane];
                unsigned long long wlo = pack2(w.x, w.y), whi = pack2(w.z, w.w);
#pragma unroll
                for (int r = 0; r < 8; ++r) {
                    const float* xf = (const float*)&xr[r];
                    float xv = xf[kk];
                    unsigned long long xx = pack2(xv, xv);
                    fma2(accLo[r], xx, wlo);
                    fma2(accHi[r], xx, whi);
                }
            }
        }
    }
    // epilogue: store row + per-head attention dots (head = lane>>3)
    float4 as4 = ((const float4*)att_s)[lane];
    float4 ad4 = ((const float4*)att_d)[lane];
#pragma unroll
    for (int r = 0; r < 8; ++r) {
        int row = rowBase + warp * 8 + r;
        float4 v;
        unpack2(accLo[r], v.x, v.y);
        unpack2(accHi[r], v.z, v.w);
        float ps = v.x * as4.x + v.y * as4.y + v.z * as4.z + v.w * as4.w;
        float pd = v.x * ad4.x + v.y * ad4.y + v.z * ad4.z + v.w * ad4.w;
#pragma unroll
        for (int o = 4; o; o >>= 1) {
            ps += __shfl_xor_sync(0xffffffffu, ps, o);
            pd += __shfl_xor_sync(0xffffffffu, pd, o);
        }
        if (row < N) {
            ((float4*)(g_xw1 + (size_t)row * 128))[lane] = v;
            if ((lane & 7) == 0) {
                g_asrc1[row * 4 + (lane >> 3)] = ps;
                g_adst1[row * 4 + (lane >> 3)] = pd;
            }
        }
    }
}

// ---------------- layer1 fused aggregate: numerator + denominator -----------
__global__ void agg1_kernel(const int* __restrict__ ei, int E, int N) {
    int warp = threadIdx.x >> 5, lane = threadIdx.x & 31;
    long e = (long)blockIdx.x * 8 + warp;
    if (e >= (long)E + N) return;
    int src, dst;
    if (e < E) { src = __ldg(ei + e); dst = __ldg(ei + E + e); }
    else       { src = (int)(e - E); dst = src; }
    int head = lane >> 3;
    float s = g_asrc1[src * 4 + head] + g_adst1[dst * 4 + head];
    float ex = __expf(leaky(s));
    float4 v = ((const float4*)(g_xw1 + (size_t)src * 128))[lane];
    v.x *= ex; v.y *= ex; v.z *= ex; v.w *= ex;
    red_add_v4(g_h + (size_t)dst * 128 + lane * 4, v);
    // one v4 red for all 4 head denominators
    float e0 = __shfl_sync(0xffffffffu, ex, 0);
    float e1 = __shfl_sync(0xffffffffu, ex, 8);
    float e2 = __shfl_sync(0xffffffffu, ex, 16);
    float e3 = __shfl_sync(0xffffffffu, ex, 24);
    if (lane == 0) red_add_v4(&g_den1[dst * 4], make_float4(e0, e1, e2, e3));
}

// ---------------- GEMM2 (fused: h=relu(num/den+b1) on load; att2 in epilogue)
// 256 thr = 8 warps x 8 rows = 64 rows/block. lanes 0..19 cover 40 cols (f32x2)
__global__ __launch_bounds__(256) void gemm2_kernel(
    const float* __restrict__ W2, const float* __restrict__ b1,
    const float* __restrict__ att_s, const float* __restrict__ att_d, int N) {
    __shared__ float sx[64][128];   // 32KB (post-activation h rows)
    __shared__ float sW[128 * 40];  // 20KB
    int rowBase = blockIdx.x * 64;
    int tid = threadIdx.x, warp = tid >> 5, lane = tid & 31;

    for (int i = tid; i < 1280; i += 256)
        ((float4*)sW)[i] = ((const float4*)W2)[i];
    for (int i = tid; i < 2048; i += 256) {
        int r = i >> 5, c4 = i & 31;
        int row = rowBase + r;
        if (row < N) {
            float4 v = ((const float4*)(g_h + (size_t)row * 128))[c4];
            float inv = 1.f / g_den1[row * 4 + (c4 >> 3)];
            float4 b = ((const float4*)b1)[c4];
            v.x = fmaxf(v.x * inv + b.x, 0.f);
            v.y = fmaxf(v.y * inv + b.y, 0.f);
            v.z = fmaxf(v.z * inv + b.z, 0.f);
            v.w = fmaxf(v.w * inv + b.w, 0.f);
            ((float4*)&sx[r][0])[c4] = v;
        } else {
            ((float4*)&sx[r][0])[c4] = make_float4(0.f, 0.f, 0.f, 0.f);
        }
    }
    __syncthreads();

    bool act = lane < 20;
    unsigned long long acc[8];
#pragma unroll
    for (int r = 0; r < 8; ++r) acc[r] = 0ull;

#pragma unroll 4
    for (int k4 = 0; k4 < 32; ++k4) {
        float4 xr[8];
#pragma unroll
        for (int r = 0; r < 8; ++r)
            xr[r] = ((float4*)&sx[warp * 8 + r][0])[k4];
#pragma unroll
        for (int kk = 0; kk < 4; ++kk) {
            unsigned long long w = 0ull;
            if (act) {
                float2 w2 = *(const float2*)&sW[(k4 * 4 + kk) * 40 + lane * 2];
                w = pack2(w2.x, w2.y);
            }
#pragma unroll
            for (int r = 0; r < 8; ++r) {
                const float* xf = (const float*)&xr[r];
                float xv = xf[kk];
                fma2(acc[r], pack2(xv, xv), w);
            }
        }
    }
    float2 as2 = act ? ((const float2*)att_s)[lane] : make_float2(0.f, 0.f);
    float2 ad2 = act ? ((const float2*)att_d)[lane] : make_float2(0.f, 0.f);
#pragma unroll
    for (int r = 0; r < 8; ++r) {
        int row = rowBase + warp * 8 + r;
        float c0, c1;
        unpack2(acc[r], c0, c1);
        float ps = c0 * as2.x + c1 * as2.y;
        float pd = c0 * ad2.x + c1 * ad2.y;
#pragma unroll
        for (int o = 16; o; o >>= 1) {
            ps += __shfl_xor_sync(0xffffffffu, ps, o);
            pd += __shfl_xor_sync(0xffffffffu, pd, o);
        }
        if (row < N) {
            if (act) *(float2*)(g_xw2 + (size_t)row * F2 + lane * 2) = make_float2(c0, c1);
            if (lane == 0) { g_asrc2[row] = ps; g_adst2[row] = pd; }
        }
    }
}

// ---------------- layer2 fused aggregate: 3 edges per warp -------------------
// lanes [0..9]=edge0, [10..19]=edge1, [20..29]=edge2, lanes 30/31 idle.
__global__ void agg2_kernel(const int* __restrict__ ei,
                            float* __restrict__ out, int E, int N) {
    int warp = threadIdx.x >> 5, lane = threadIdx.x & 31;
    int grp = lane / 10, gl = lane - grp * 10;       // grp 0..3 (3 = idle)
    long e = (long)blockIdx.x * 24 + warp * 3 + grp;
    long EP = (long)E + N;
    if (grp >= 3 || e >= EP) return;
    int src, dst;
    if (e < E) { src = __ldg(ei + e); dst = __ldg(ei + E + e); }   // HW broadcast within group
    else       { src = (int)(e - E); dst = src; }
    float s = g_asrc2[src] + g_adst2[dst];
    float ex = __expf(leaky(s));
    float4 v = ((const float4*)(g_xw2 + (size_t)src * F2))[gl];
    v.x *= ex; v.y *= ex; v.z *= ex; v.w *= ex;
    red_add_v4(out + (size_t)dst * F2 + gl * 4, v);
    if (gl == 0) red_add_f32(&g_den2[dst], ex);
}

// ---------------- final: out = out/den2 + b2 ---------------------------------
__global__ void final_kernel(float* __restrict__ out, const float* __restrict__ b2,
                             int N) {
    size_t total = (size_t)N * F2;
    for (size_t i = (size_t)blockIdx.x * blockDim.x + threadIdx.x; i < total;
         i += (size_t)gridDim.x * blockDim.x) {
        size_t n = i / F2;
        int c = (int)(i - n * F2);
        out[i] = out[i] / g_den2[n] + b2[c];
    }
}

// ============================================================================
extern "C" void kernel_launch(void* const* d_in, const int* in_sizes, int n_in,
                              void* d_out, int out_size) {
    const float* x   = (const float*)d_in[0];
    const int*   ei  = (const int*)d_in[1];   // int32 (JAX default-config downcast)
    const float* W1  = (const float*)d_in[2];
    const float* as1 = (const float*)d_in[3];
    const float* ad1 = (const float*)d_in[4];
    const float* b1  = (const float*)d_in[5];
    const float* W2  = (const float*)d_in[6];
    const float* as2 = (const float*)d_in[7];
    const float* ad2 = (const float*)d_in[8];
    const float* b2  = (const float*)d_in[9];
    float*       out = (float*)d_out;

    int N  = in_sizes[0] / DIM1;   // 100000
    int E  = in_sizes[1] / 2;      // 1600000
    int EP = E + N;

    zero_kernel <<<4096, 256>>>(out, N);
    gemm1_kernel<<<(N + 63) / 64, 256>>>(x, W1, as1, ad1, N);
    agg1_kernel <<<(EP + 7) / 8, 256>>>(ei, E, N);
    gemm2_kernel<<<(N + 63) / 64, 256>>>(W2, b1, as2, ad2, N);
    agg2_kernel <<<(EP + 23) / 24, 256>>>(ei, out, E, N);
    final_kernel<<<2048, 256>>>(out, b2, N);
}